// round 5
// baseline (speedup 1.0000x reference)
#include <cuda_runtime.h>
#include <cuda_bf16.h>
#include <cstdint>

// NeighborListForTraining: all intra-molecule ordered pairs (i!=j) for
// 2000 molecules x 64 atoms. Output (float32, concatenated flat):
//   [0,P) i_idx | [P,2P) j_idx | [2P,3P) d_ij | [3P,6P) r_ij[P][3]
// P = n_mols * 4032 = 8,064,000.
//
// R5: three register-store kernels all pinned at 41us / L1~72% / DRAM~41%.
// Model: the STG sector path (~32B/cyc/SM) is the wall. This version stages
// each 1008-pair tile in SMEM and drains it with cp.async.bulk S2G (TMA),
// double-buffered, bypassing the register-store path entirely.

#define NPM    64
#define PPM    4032           // pairs per molecule
#define TILES  4
#define TPP    1008           // pairs per tile
#define TGR    252            // thread-groups (4 pairs) per tile
#define BLOCK  256
#define CUTOFF 5.0f

// dynamic SMEM layout (floats):
//  [0,256)                    s_pos: float4[64]
//  buf b in {0,1} at 256+b*6048:
//    +0     i[1008] | +1008 j[1008] | +2016 d[1008] | +3024 r[3024]
#define SM_BUF_OFF   256
#define SM_BUF_FLTS  6048
#define SMEM_BYTES   ((SM_BUF_OFF + 2 * SM_BUF_FLTS) * 4)   // 49408

__device__ __forceinline__ uint32_t sptr(const void* p) {
    return (uint32_t)__cvta_generic_to_shared((void*)p);
}

__device__ __forceinline__ void bulk_s2g(void* gptr, uint32_t saddr, uint32_t bytes) {
    asm volatile("cp.async.bulk.global.shared::cta.bulk_group [%0], [%1], %2;"
                 :: "l"(gptr), "r"(saddr), "r"(bytes) : "memory");
}

__global__ __launch_bounds__(BLOCK) void neighborlist_kernel(
    const float* __restrict__ pos,   // [n_atoms, 3]
    float* __restrict__ out,
    int n_mols)
{
    extern __shared__ float smem[];
    float4* s_pos = (float4*)smem;

    const int tid = threadIdx.x;
    const int mol = blockIdx.x;
    const float* mp = pos + (size_t)mol * (NPM * 3);

    // Stage this molecule's 64 positions (float4 slots).
    if (tid < NPM)
        s_pos[tid] = make_float4(mp[3 * tid + 0], mp[3 * tid + 1],
                                 mp[3 * tid + 2], 0.0f);
    __syncthreads();

    const long long P = (long long)n_mols * PPM;
    float* __restrict__ out_i = out;
    float* __restrict__ out_j = out + P;
    float* __restrict__ out_d = out + 2 * P;
    float* __restrict__ out_r = out + 3 * P;

    const float atom_basef = (float)(mol * NPM);
    const long long mol_pair_base = (long long)mol * PPM;

    for (int tile = 0; tile < TILES; ++tile) {
        const int buf = tile & 1;
        float* sb = smem + SM_BUF_OFF + buf * SM_BUF_FLTS;

        // Before reusing a buffer, make sure the bulk copy two tiles ago
        // has finished READING it.
        if (tile >= 2) {
            if (tid == 0)
                asm volatile("cp.async.bulk.wait_group.read 1;" ::: "memory");
            __syncthreads();
        }

        if (tid < TGR) {
            const int pbase = tile * TPP + tid * 4;   // local pair index

            float4 fi, fj, fd;
            float  rr[12];
            float* fip = (float*)&fi;
            float* fjp = (float*)&fj;
            float* fdp = (float*)&fd;

            #pragma unroll
            for (int k = 0; k < 4; k++) {
                const int t  = pbase + k;          // 0..4031
                const int il = t / 63;
                const int rm = t - il * 63;
                const int jl = rm + (rm >= il);

                const float4 pi = s_pos[il];
                const float4 pj = s_pos[jl];

                float dx = pj.x - pi.x;
                float dy = pj.y - pi.y;
                float dz = pj.z - pi.z;
                float d  = sqrtf(dx * dx + dy * dy + dz * dz);

                if (!(d <= CUTOFF)) { d = 0.0f; dx = 0.0f; dy = 0.0f; dz = 0.0f; }

                fip[k] = atom_basef + (float)il;
                fjp[k] = atom_basef + (float)jl;
                fdp[k] = d;
                rr[3 * k + 0] = dx;
                rr[3 * k + 1] = dy;
                rr[3 * k + 2] = dz;
            }

            ((float4*)(sb          ))[tid] = fi;
            ((float4*)(sb + TPP    ))[tid] = fj;
            ((float4*)(sb + 2 * TPP))[tid] = fd;
            float4* rp = (float4*)(sb + 3 * TPP) + tid * 3;
            rp[0] = *(float4*)(rr + 0);
            rp[1] = *(float4*)(rr + 4);
            rp[2] = *(float4*)(rr + 8);
        }
        __syncthreads();

        if (tid == 0) {
            const long long p = mol_pair_base + (long long)tile * TPP;
            asm volatile("fence.proxy.async;" ::: "memory");
            bulk_s2g(out_i + p,     sptr(sb          ), TPP * 4);
            bulk_s2g(out_j + p,     sptr(sb + TPP    ), TPP * 4);
            bulk_s2g(out_d + p,     sptr(sb + 2 * TPP), TPP * 4);
            bulk_s2g(out_r + 3 * p, sptr(sb + 3 * TPP), TPP * 12);
            asm volatile("cp.async.bulk.commit_group;" ::: "memory");
        }
    }

    // All bulk stores must fully complete before kernel end.
    if (tid == 0)
        asm volatile("cp.async.bulk.wait_group 0;" ::: "memory");
}

extern "C" void kernel_launch(void* const* d_in, const int* in_sizes, int n_in,
                              void* d_out, int out_size)
{
    const float* positions = (const float*)d_in[0];
    const int n_atoms = in_sizes[0] / 3;
    const int n_mols  = n_atoms / NPM;

    cudaFuncSetAttribute(neighborlist_kernel,
                         cudaFuncAttributeMaxDynamicSharedMemorySize, SMEM_BYTES);

    float* out = (float*)d_out;
    neighborlist_kernel<<<n_mols, BLOCK, SMEM_BYTES>>>(positions, out, n_mols);
}